// round 13
// baseline (speedup 1.0000x reference)
#include <cuda_runtime.h>
#include <cuda_fp16.h>
#include <cstdint>

// ---------------------------------------------------------------------------
// y[8192,16384] = x[8192,4096] @ dequant(W[4096,16384]) * scale + bias
// Weight arrives as int32 (harness dtype set is f32/i32/bf16).
// R13: persistent CTAs (grid=296, 2/SM), continuous cp.async fill stream
//      across tile boundaries -> next tile's prologue hides under this tile's
//      epilogue. Base: 128x128 tile, 4 warps @ 64x64, 3-stage BK=64.
// ---------------------------------------------------------------------------
static constexpr int M_ROWS = 8192;
static constexpr int K_DIM  = 4096;
static constexpr int N_DIM  = 16384;

static constexpr int BM = 128;
static constexpr int BN = 128;
static constexpr int BK = 64;
static constexpr int NITER  = K_DIM / BK;     // 64
static constexpr int KSTEPS = BK / 16;        // 4
static constexpr int NTILES = (M_ROWS / BM) * (N_DIM / BN);   // 8192
static constexpr int GRID   = 296;            // 2 CTAs x 148 SMs

static constexpr int A_LD = BK + 8;           // 72 halves = 144 B
static constexpr int B_LD = BK + 8;
static constexpr int A_ST = BM * A_LD;        // 9216 halves
static constexpr int B_ST = BN * B_LD;        // 9216 halves
static constexpr int STG  = A_ST + B_ST;      // 18432 halves = 36864 B
static constexpr int SMEM_BYTES = 3 * STG * 2;   // 110592 B -> 2 CTAs/SM

__device__ __half g_xh[(size_t)M_ROWS * K_DIM];   //  64 MiB  [M][K]
__device__ __half g_wh[(size_t)N_DIM * K_DIM];    // 128 MiB  [N][K]

// ---------------------------------------------------------------------------
__device__ __forceinline__ uint32_t smem_u32(const void* p) {
    uint32_t a;
    asm("{ .reg .u64 t; cvta.to.shared.u64 t, %1; cvt.u32.u64 %0, t; }" : "=r"(a) : "l"(p));
    return a;
}

__device__ __forceinline__ void cp16(uint32_t dst, const void* src) {
    asm volatile("cp.async.cg.shared.global [%0], [%1], 16;" :: "r"(dst), "l"(src));
}

#define CP_COMMIT() asm volatile("cp.async.commit_group;" ::: "memory")

__device__ __forceinline__ void ldsm4(uint32_t* r, uint32_t addr) {
    asm volatile("ldmatrix.sync.aligned.m8n8.x4.shared.b16 {%0,%1,%2,%3}, [%4];"
                 : "=r"(r[0]), "=r"(r[1]), "=r"(r[2]), "=r"(r[3]) : "r"(addr));
}

__device__ __forceinline__ void mma16816(float* d, const uint32_t* a, uint32_t b0, uint32_t b1) {
    asm volatile(
        "mma.sync.aligned.m16n8k16.row.col.f32.f16.f16.f32 "
        "{%0,%1,%2,%3}, {%4,%5,%6,%7}, {%8,%9}, {%0,%1,%2,%3};"
        : "+f"(d[0]), "+f"(d[1]), "+f"(d[2]), "+f"(d[3])
        : "r"(a[0]), "r"(a[1]), "r"(a[2]), "r"(a[3]), "r"(b0), "r"(b1));
}

__device__ __forceinline__ void stcs2(float* p, float vx, float vy) {
    asm volatile("st.global.cs.v2.f32 [%0], {%1, %2};" :: "l"(p), "f"(vx), "f"(vy) : "memory");
}

// ---------------------------------------------------------------------------
// Fused prep kernel
// ---------------------------------------------------------------------------
static constexpr int XB   = (M_ROWS * K_DIM / 4) / 256;   // 32768 blocks
static constexpr int WBX  = N_DIM / 32;                   // 512
static constexpr int WBY  = K_DIM / 64;                   // 64

__global__ void cvt_fused_kernel(const float4* __restrict__ x,
                                 const int* __restrict__ w,
                                 __half2* __restrict__ xh,
                                 __half* __restrict__ wh) {
    if (blockIdx.x < XB) {
        int i = blockIdx.x * 256 + threadIdx.x;
        float4 v = x[i];
        xh[2 * i]     = __floats2half2_rn(v.x, v.y);
        xh[2 * i + 1] = __floats2half2_rn(v.z, v.w);
    } else {
        __shared__ int t[64][33];
        int wb = blockIdx.x - XB;
        int n0 = (wb % WBX) * 32;
        int k0 = (wb / WBX) * 64;
        int tx = threadIdx.x & 31, ty = threadIdx.x >> 5;
        #pragma unroll
        for (int j = 0; j < 8; ++j) {
            int k = ty + 8 * j;
            t[k][tx] = w[(size_t)(k0 + k) * N_DIM + n0 + tx];
        }
        __syncthreads();
        #pragma unroll
        for (int j = 0; j < 4; ++j) {
            int i = ty + 8 * j;
            __half2 v = __halves2half2(__int2half_rn(t[2 * tx][i]),
                                       __int2half_rn(t[2 * tx + 1][i]));
            *reinterpret_cast<__half2*>(wh + (size_t)(n0 + i) * K_DIM + k0 + 2 * tx) = v;
        }
    }
}

// ---------------------------------------------------------------------------
// Main GEMM — persistent CTAs
// ---------------------------------------------------------------------------
__global__ void __launch_bounds__(128, 2) qgemm_kernel(
    const float* __restrict__ scale,
    const float* __restrict__ bias,
    float* __restrict__ out)
{
    extern __shared__ __align__(16) char smem_raw[];
    const uint32_t sb = smem_u32(smem_raw);
    const int tid = threadIdx.x;
    const int wid = tid >> 5;
    const int lid = tid & 31;

    // Per-thread fill addressing components (tile-independent parts)
    const int fa_row = tid >> 3, fa_cc = (tid & 7);
    const uint32_t a_dst0 = (uint32_t)(fa_row * A_LD + fa_cc * 8) * 2;
    const uint32_t b_dst0 = (uint32_t)(A_ST + fa_row * B_LD + fa_cc * 8) * 2;

    const int wmb = (wid & 1) * 64;
    const int wnb = (wid >> 1) * 64;

    const int a_row_lane = lid & 15;
    const int a_col_lane = (lid >> 4) * 8;
    const int b_row_lane = (lid & 7) | ((lid >> 4) << 3);
    const int b_col_lane = ((lid >> 3) & 1) * 8;
    const uint32_t a_off = (uint32_t)((wmb + a_row_lane) * A_LD + a_col_lane) * 2;
    const uint32_t b_off = (uint32_t)(A_ST + (wnb + b_row_lane) * B_LD + b_col_lane) * 2;

    auto tile_coords = [](int tile, int& m0, int& n0) {
        int group  = tile >> 9;
        int within = tile & 511;
        n0 = ((group << 3) | (within & 7)) * BN;
        m0 = (within >> 3) * BM;
    };

    auto fill_base = [&](int m0, int n0) -> const __half* {
        return nullptr;  // unused; pointers computed inline below
    };
    (void)fill_base;

    // Rotating stage bases (continuous across tiles)
    uint32_t s0 = sb;
    uint32_t s1 = sb + (uint32_t)(STG * 2);
    uint32_t s2 = sb + (uint32_t)(2 * STG * 2);

    int tile = blockIdx.x;
    int m0, n0;
    tile_coords(tile, m0, n0);
    const __half* xrow = g_xh + (size_t)(m0 + fa_row) * K_DIM + fa_cc * 8;
    const __half* wrow = g_wh + (size_t)(n0 + fa_row) * K_DIM + fa_cc * 8;

    // Prologue: fill iterations g=0,1 of the first tile
    #pragma unroll
    for (int s = 0; s < 2; ++s) {
        const uint32_t base = (s == 0) ? s0 : s1;
        const int k0 = s * BK;
        #pragma unroll
        for (int p = 0; p < 2 * KSTEPS; ++p) {
            int r = p * 16;
            cp16(base + a_dst0 + (uint32_t)(r * A_LD) * 2, xrow + (size_t)r * K_DIM + k0);
            cp16(base + b_dst0 + (uint32_t)(r * B_LD) * 2, wrow + (size_t)r * K_DIM + k0);
        }
        CP_COMMIT();
    }
    asm volatile("cp.async.wait_group 1;" ::: "memory");

    #pragma unroll 1
    while (true) {
        const int tile_next = tile + GRID;
        const bool has_next = tile_next < NTILES;
        int m0n = 0, n0n = 0;
        if (has_next) tile_coords(tile_next, m0n, n0n);
        const __half* xrow_n = has_next
            ? g_xh + (size_t)(m0n + fa_row) * K_DIM + fa_cc * 8 : nullptr;
        const __half* wrow_n = has_next
            ? g_wh + (size_t)(n0n + fa_row) * K_DIM + fa_cc * 8 : nullptr;

        float acc[4][8][4];
        #pragma unroll
        for (int i = 0; i < 4; ++i)
            #pragma unroll
            for (int j = 0; j < 8; ++j)
                #pragma unroll
                for (int k = 0; k < 4; ++k) acc[i][j][k] = 0.0f;

        #pragma unroll 1
        for (int it = 0; it < NITER; ++it) {
            __syncthreads();
            // Fill target: iteration it+2 of the continuous stream
            const __half* xp;
            const __half* wp;
            bool do_fill;
            if (it < NITER - 2) {
                xp = xrow + (it + 2) * BK;
                wp = wrow + (it + 2) * BK;
                do_fill = true;
            } else if (has_next) {
                xp = xrow_n + (it + 2 - NITER) * BK;
                wp = wrow_n + (it + 2 - NITER) * BK;
                do_fill = true;
            } else {
                xp = nullptr; wp = nullptr; do_fill = false;
            }

            #pragma unroll
            for (int ks = 0; ks < KSTEPS; ++ks) {
                uint32_t a[4][4], b[4][4];
                #pragma unroll
                for (int mf = 0; mf < 4; ++mf)
                    ldsm4(a[mf], s0 + a_off + (uint32_t)(mf * 16 * A_LD + ks * 16) * 2);
                #pragma unroll
                for (int nf2 = 0; nf2 < 4; ++nf2)
                    ldsm4(b[nf2], s0 + b_off + (uint32_t)(nf2 * 16 * B_LD + ks * 16) * 2);
                if (do_fill) {
                    #pragma unroll
                    for (int j = 0; j < 2; ++j) {
                        int r = (ks * 2 + j) * 16;
                        cp16(s2 + a_dst0 + (uint32_t)(r * A_LD) * 2, xp + (size_t)r * K_DIM);
                        cp16(s2 + b_dst0 + (uint32_t)(r * B_LD) * 2, wp + (size_t)r * K_DIM);
                    }
                }
                if (ks == KSTEPS - 1) CP_COMMIT();
                #pragma unroll
                for (int mf = 0; mf < 4; ++mf) {
                    #pragma unroll
                    for (int nf2 = 0; nf2 < 4; ++nf2) {
                        mma16816(acc[mf][nf2 * 2],     a[mf], b[nf2][0], b[nf2][1]);
                        mma16816(acc[mf][nf2 * 2 + 1], a[mf], b[nf2][2], b[nf2][3]);
                    }
                }
            }
            // Drain own next group while the tail MMAs execute
            asm volatile("cp.async.wait_group 1;" ::: "memory");
            uint32_t t = s0; s0 = s1; s1 = s2; s2 = t;
        }

        // ---- Epilogue (no smem): next tile's fills land meanwhile ----
        {
            const int ncol0 = n0 + wnb;
            float2 sc[8], bi[8];
            #pragma unroll
            for (int nf = 0; nf < 8; ++nf) {
                int c = nf * 8 + (lid & 3) * 2;
                sc[nf] = *reinterpret_cast<const float2*>(scale + ncol0 + c);
                bi[nf] = *reinterpret_cast<const float2*>(bias + ncol0 + c);
            }
            #pragma unroll
            for (int mf = 0; mf < 4; ++mf) {
                int r0 = m0 + wmb + mf * 16 + (lid >> 2);
                float* out0 = out + (size_t)r0 * N_DIM + ncol0;
                float* out1 = out0 + (size_t)8 * N_DIM;
                #pragma unroll
                for (int nf = 0; nf < 8; ++nf) {
                    int c = nf * 8 + (lid & 3) * 2;
                    stcs2(out0 + c, fmaf(acc[mf][nf][0], sc[nf].x, bi[nf].x),
                                    fmaf(acc[mf][nf][1], sc[nf].y, bi[nf].y));
                    stcs2(out1 + c, fmaf(acc[mf][nf][2], sc[nf].x, bi[nf].x),
                                    fmaf(acc[mf][nf][3], sc[nf].y, bi[nf].y));
                }
            }
        }

        if (!has_next) break;
        tile = tile_next; m0 = m0n; n0 = n0n; xrow = xrow_n; wrow = wrow_n;
    }
}

// ---------------------------------------------------------------------------
// Host launch — inputs identified by element count.
// ---------------------------------------------------------------------------
extern "C" void kernel_launch(void* const* d_in, const int* in_sizes, int n_in,
                              void* d_out, int out_size) {
    int xi = 0, wi = 1, sm1 = -1, sm2 = -1;
    for (int i = 0; i < 4; ++i) {
        if (in_sizes[i] == M_ROWS * K_DIM)      xi = i;
        else if (in_sizes[i] == K_DIM * N_DIM)  wi = i;
        else if (sm1 < 0)                       sm1 = i;
        else                                    sm2 = i;
    }
    int si, bi2;
    if (xi < sm1) { si = sm1; bi2 = sm2; }   // dict order: x, w, scale, bias
    else          { bi2 = sm1; si = sm2; }

    const float* x     = (const float*)d_in[xi];
    const int*   w     = (const int*)d_in[wi];
    const float* scale = (const float*)d_in[si];
    const float* bias  = (const float*)d_in[bi2];
    float*       out   = (float*)d_out;

    void* xh = nullptr; cudaGetSymbolAddress(&xh, g_xh);
    void* wh = nullptr; cudaGetSymbolAddress(&wh, g_wh);

    cvt_fused_kernel<<<XB + WBX * WBY, 256>>>((const float4*)x, w,
                                              (__half2*)xh, (__half*)wh);

    cudaFuncSetAttribute(qgemm_kernel, cudaFuncAttributeMaxDynamicSharedMemorySize,
                         SMEM_BYTES);
    qgemm_kernel<<<GRID, 128, SMEM_BYTES>>>(scale, bias, out);
}

// round 14
// speedup vs baseline: 1.0757x; 1.0757x over previous
#include <cuda_runtime.h>
#include <cuda_fp16.h>
#include <cstdint>

// ---------------------------------------------------------------------------
// y[8192,16384] = x[8192,4096] @ dequant(W[4096,16384]) * scale + bias
// Weight arrives as int32 (harness dtype set is f32/i32/bf16).
// R14: R12 base (persistence reverted) + split fill commits (2 groups/iter,
//      wait_group 2 -> earlier DMA start, smoother LTS) + scale/bias prefetch.
// Base: 128x128 tile, 4 warps @ 64x64, 3-stage BK=64, 2 CTAs/SM.
// ---------------------------------------------------------------------------
static constexpr int M_ROWS = 8192;
static constexpr int K_DIM  = 4096;
static constexpr int N_DIM  = 16384;

static constexpr int BM = 128;
static constexpr int BN = 128;
static constexpr int BK = 64;
static constexpr int STAGES = 3;
static constexpr int NITER  = K_DIM / BK;     // 64
static constexpr int KSTEPS = BK / 16;        // 4

static constexpr int A_LD = BK + 8;           // 72 halves = 144 B
static constexpr int B_LD = BK + 8;
static constexpr int A_ST = BM * A_LD;        // 9216 halves
static constexpr int B_ST = BN * B_LD;        // 9216 halves
static constexpr int STG  = A_ST + B_ST;      // 18432 halves = 36864 B
static constexpr int SMEM_BYTES = STAGES * STG * 2;   // 110592 B -> 2 CTAs/SM

__device__ __half g_xh[(size_t)M_ROWS * K_DIM];   //  64 MiB  [M][K]
__device__ __half g_wh[(size_t)N_DIM * K_DIM];    // 128 MiB  [N][K]

// ---------------------------------------------------------------------------
__device__ __forceinline__ uint32_t smem_u32(const void* p) {
    uint32_t a;
    asm("{ .reg .u64 t; cvta.to.shared.u64 t, %1; cvt.u32.u64 %0, t; }" : "=r"(a) : "l"(p));
    return a;
}

__device__ __forceinline__ void cp16(uint32_t dst, const void* src) {
    asm volatile("cp.async.cg.shared.global [%0], [%1], 16;" :: "r"(dst), "l"(src));
}

#define CP_COMMIT() asm volatile("cp.async.commit_group;" ::: "memory")

__device__ __forceinline__ void ldsm4(uint32_t* r, uint32_t addr) {
    asm volatile("ldmatrix.sync.aligned.m8n8.x4.shared.b16 {%0,%1,%2,%3}, [%4];"
                 : "=r"(r[0]), "=r"(r[1]), "=r"(r[2]), "=r"(r[3]) : "r"(addr));
}

__device__ __forceinline__ void mma16816(float* d, const uint32_t* a, uint32_t b0, uint32_t b1) {
    asm volatile(
        "mma.sync.aligned.m16n8k16.row.col.f32.f16.f16.f32 "
        "{%0,%1,%2,%3}, {%4,%5,%6,%7}, {%8,%9}, {%0,%1,%2,%3};"
        : "+f"(d[0]), "+f"(d[1]), "+f"(d[2]), "+f"(d[3])
        : "r"(a[0]), "r"(a[1]), "r"(a[2]), "r"(a[3]), "r"(b0), "r"(b1));
}

__device__ __forceinline__ void stcs2(float* p, float vx, float vy) {
    asm volatile("st.global.cs.v2.f32 [%0], {%1, %2};" :: "l"(p), "f"(vx), "f"(vy) : "memory");
}

// ---------------------------------------------------------------------------
// Fused prep kernel (x convert + coalesced W transpose)
// ---------------------------------------------------------------------------
static constexpr int XB   = (M_ROWS * K_DIM / 4) / 256;   // 32768 blocks
static constexpr int WBX  = N_DIM / 32;                   // 512
static constexpr int WBY  = K_DIM / 64;                   // 64

__global__ void cvt_fused_kernel(const float4* __restrict__ x,
                                 const int* __restrict__ w,
                                 __half2* __restrict__ xh,
                                 __half* __restrict__ wh) {
    if (blockIdx.x < XB) {
        int i = blockIdx.x * 256 + threadIdx.x;
        float4 v = x[i];
        xh[2 * i]     = __floats2half2_rn(v.x, v.y);
        xh[2 * i + 1] = __floats2half2_rn(v.z, v.w);
    } else {
        __shared__ int t[64][33];
        int wb = blockIdx.x - XB;
        int n0 = (wb % WBX) * 32;
        int k0 = (wb / WBX) * 64;
        int tx = threadIdx.x & 31, ty = threadIdx.x >> 5;
        #pragma unroll
        for (int j = 0; j < 8; ++j) {
            int k = ty + 8 * j;
            t[k][tx] = w[(size_t)(k0 + k) * N_DIM + n0 + tx];
        }
        __syncthreads();
        #pragma unroll
        for (int j = 0; j < 4; ++j) {
            int i = ty + 8 * j;
            __half2 v = __halves2half2(__int2half_rn(t[2 * tx][i]),
                                       __int2half_rn(t[2 * tx + 1][i]));
            *reinterpret_cast<__half2*>(wh + (size_t)(n0 + i) * K_DIM + k0 + 2 * tx) = v;
        }
    }
}

// ---------------------------------------------------------------------------
// Main GEMM
// ---------------------------------------------------------------------------
__global__ void __launch_bounds__(128, 2) qgemm_kernel(
    const float* __restrict__ scale,
    const float* __restrict__ bias,
    float* __restrict__ out)
{
    extern __shared__ __align__(16) char smem_raw[];
    const uint32_t sb = smem_u32(smem_raw);
    const int tid = threadIdx.x;
    const int wid = tid >> 5;
    const int lid = tid & 31;

    const int bid = blockIdx.x;
    const int group  = bid >> 9;
    const int within = bid & 511;
    const int nt = (group << 3) | (within & 7);
    const int mt = within >> 3;
    const int m0 = mt * BM;
    const int n0 = nt * BN;

    const __half* __restrict__ xh = g_xh;
    const __half* __restrict__ wh = g_wh;

    // Per-thread fill addressing
    const int fa_row = tid >> 3, fa_cc = (tid & 7);
    const __half* xrow = xh + (size_t)(m0 + fa_row) * K_DIM + fa_cc * 8;
    const __half* wrow = wh + (size_t)(n0 + fa_row) * K_DIM + fa_cc * 8;
    const uint32_t a_dst0 = (uint32_t)(fa_row * A_LD + fa_cc * 8) * 2;
    const uint32_t b_dst0 = (uint32_t)(A_ST + fa_row * B_LD + fa_cc * 8) * 2;

    const int wmb = (wid & 1) * 64;
    const int wnb = (wid >> 1) * 64;

    // Prefetch scale/bias for this warp's columns (latency hides under mainloop)
    const int ncol0 = n0 + wnb;
    float2 sc[8], bi[8];
    #pragma unroll
    for (int nf = 0; nf < 8; ++nf) {
        int c = nf * 8 + (lid & 3) * 2;
        sc[nf] = *reinterpret_cast<const float2*>(scale + ncol0 + c);
        bi[nf] = *reinterpret_cast<const float2*>(bias + ncol0 + c);
    }

    float acc[4][8][4];
    #pragma unroll
    for (int i = 0; i < 4; ++i)
        #pragma unroll
        for (int j = 0; j < 8; ++j)
            #pragma unroll
            for (int k = 0; k < 4; ++k) acc[i][j][k] = 0.0f;

    // Rotating stage bases
    uint32_t s0 = sb;
    uint32_t s1 = sb + (uint32_t)(STG * 2);
    uint32_t s2 = sb + (uint32_t)(2 * STG * 2);

    // Prologue: full fills of stages 0 and 1 (two commit groups each)
    #pragma unroll
    for (int s = 0; s < 2; ++s) {
        const uint32_t base = (s == 0) ? s0 : s1;
        const int k0 = s * BK;
        #pragma unroll
        for (int h = 0; h < 2; ++h) {
            #pragma unroll
            for (int p = 0; p < KSTEPS; ++p) {
                int r = (h * KSTEPS + p) * 16;
                cp16(base + a_dst0 + (uint32_t)(r * A_LD) * 2, xrow + (size_t)r * K_DIM + k0);
                cp16(base + b_dst0 + (uint32_t)(r * B_LD) * 2, wrow + (size_t)r * K_DIM + k0);
            }
            CP_COMMIT();
        }
    }

    const int a_row_lane = lid & 15;
    const int a_col_lane = (lid >> 4) * 8;
    const int b_row_lane = (lid & 7) | ((lid >> 4) << 3);
    const int b_col_lane = ((lid >> 3) & 1) * 8;

    const uint32_t a_off = (uint32_t)((wmb + a_row_lane) * A_LD + a_col_lane) * 2;
    const uint32_t b_off = (uint32_t)(A_ST + (wnb + b_row_lane) * B_LD + b_col_lane) * 2;

    int kf = 2 * BK;   // fill k-offset for stage it+2

    // Drain stage-0 groups for this thread; barrier publishes across threads.
    asm volatile("cp.async.wait_group 2;" ::: "memory");

    #pragma unroll 1
    for (int it = 0; it < NITER; ++it) {
        __syncthreads();
        const bool do_fill = (it + 2 < NITER);
        const __half* xp = xrow + kf;
        const __half* wp = wrow + kf;

        #pragma unroll
        for (int ks = 0; ks < KSTEPS; ++ks) {
            uint32_t a[4][4], b[4][4];
            #pragma unroll
            for (int mf = 0; mf < 4; ++mf)
                ldsm4(a[mf], s0 + a_off + (uint32_t)(mf * 16 * A_LD + ks * 16) * 2);
            #pragma unroll
            for (int nf2 = 0; nf2 < 4; ++nf2)
                ldsm4(b[nf2], s0 + b_off + (uint32_t)(nf2 * 16 * B_LD + ks * 16) * 2);
            // quarter of stage it+2 fill, hidden in the ldsm->mma shadow
            if (do_fill) {
                #pragma unroll
                for (int j = 0; j < 2; ++j) {
                    int r = (ks * 2 + j) * 16;
                    cp16(s2 + a_dst0 + (uint32_t)(r * A_LD) * 2, xp + (size_t)r * K_DIM);
                    cp16(s2 + b_dst0 + (uint32_t)(r * B_LD) * 2, wp + (size_t)r * K_DIM);
                }
            }
            // Two commit groups per iteration: DMA of the first half starts
            // mid-iteration instead of at the end.
            if (ks == 1 || ks == KSTEPS - 1) CP_COMMIT();
            #pragma unroll
            for (int mf = 0; mf < 4; ++mf) {
                #pragma unroll
                for (int nf2 = 0; nf2 < 4; ++nf2) {
                    mma16816(acc[mf][nf2 * 2],     a[mf], b[nf2][0], b[nf2][1]);
                    mma16816(acc[mf][nf2 * 2 + 1], a[mf], b[nf2][2], b[nf2][3]);
                }
            }
        }
        // Allow this iteration's 2 groups outstanding; everything older (which
        // includes all of stage it+1's fills) is drained under the MMA tail.
        asm volatile("cp.async.wait_group 2;" ::: "memory");
        uint32_t t = s0; s0 = s1; s1 = s2; s2 = t;
        kf += BK;
    }

    // ---- Epilogue: fused scale/bias (prefetched), streaming stores ----
    #pragma unroll
    for (int mf = 0; mf < 4; ++mf) {
        int r0 = m0 + wmb + mf * 16 + (lid >> 2);
        float* out0 = out + (size_t)r0 * N_DIM + ncol0;
        float* out1 = out0 + (size_t)8 * N_DIM;
        #pragma unroll
        for (int nf = 0; nf < 8; ++nf) {
            int c = nf * 8 + (lid & 3) * 2;
            stcs2(out0 + c, fmaf(acc[mf][nf][0], sc[nf].x, bi[nf].x),
                            fmaf(acc[mf][nf][1], sc[nf].y, bi[nf].y));
            stcs2(out1 + c, fmaf(acc[mf][nf][2], sc[nf].x, bi[nf].x),
                            fmaf(acc[mf][nf][3], sc[nf].y, bi[nf].y));
        }
    }
}

// ---------------------------------------------------------------------------
// Host launch — inputs identified by element count.
// ---------------------------------------------------------------------------
extern "C" void kernel_launch(void* const* d_in, const int* in_sizes, int n_in,
                              void* d_out, int out_size) {
    int xi = 0, wi = 1, sm1 = -1, sm2 = -1;
    for (int i = 0; i < 4; ++i) {
        if (in_sizes[i] == M_ROWS * K_DIM)      xi = i;
        else if (in_sizes[i] == K_DIM * N_DIM)  wi = i;
        else if (sm1 < 0)                       sm1 = i;
        else                                    sm2 = i;
    }
    int si, bi2;
    if (xi < sm1) { si = sm1; bi2 = sm2; }   // dict order: x, w, scale, bias
    else          { bi2 = sm1; si = sm2; }

    const float* x     = (const float*)d_in[xi];
    const int*   w     = (const int*)d_in[wi];
    const float* scale = (const float*)d_in[si];
    const float* bias  = (const float*)d_in[bi2];
    float*       out   = (float*)d_out;

    void* xh = nullptr; cudaGetSymbolAddress(&xh, g_xh);
    void* wh = nullptr; cudaGetSymbolAddress(&wh, g_wh);

    cvt_fused_kernel<<<XB + WBX * WBY, 256>>>((const float4*)x, w,
                                              (__half2*)xh, (__half*)wh);

    cudaFuncSetAttribute(qgemm_kernel, cudaFuncAttributeMaxDynamicSharedMemorySize,
                         SMEM_BYTES);
    int grid = (M_ROWS / BM) * (N_DIM / BN);   // 8192
    qgemm_kernel<<<grid, 128, SMEM_BYTES>>>(scale, bias, out);
}

// round 15
// speedup vs baseline: 1.1308x; 1.0513x over previous
#include <cuda_runtime.h>
#include <cuda_fp16.h>
#include <cstdint>

// ---------------------------------------------------------------------------
// y[8192,16384] = x[8192,4096] @ dequant(W[4096,16384]) * scale + bias
// Weight arrives as int32 (harness dtype set is f32/i32/bf16).
// R15: mainloop unrolled in triples with STATIC stage bases (rotation period
//      3) -> no rotation MOVs, compile-time smem addressing, 3-iter window.
// Base: 128x128 tile, 4 warps @ 64x64, 3-stage BK=64, 2 CTAs/SM (R14 core).
// ---------------------------------------------------------------------------
static constexpr int M_ROWS = 8192;
static constexpr int K_DIM  = 4096;
static constexpr int N_DIM  = 16384;

static constexpr int BM = 128;
static constexpr int BN = 128;
static constexpr int BK = 64;
static constexpr int STAGES = 3;
static constexpr int NITER  = K_DIM / BK;     // 64
static constexpr int KSTEPS = BK / 16;        // 4

static constexpr int A_LD = BK + 8;           // 72 halves = 144 B
static constexpr int B_LD = BK + 8;
static constexpr int A_ST = BM * A_LD;        // 9216 halves
static constexpr int B_ST = BN * B_LD;        // 9216 halves
static constexpr int STG  = A_ST + B_ST;      // 18432 halves = 36864 B
static constexpr int SMEM_BYTES = STAGES * STG * 2;   // 110592 B -> 2 CTAs/SM

__device__ __half g_xh[(size_t)M_ROWS * K_DIM];   //  64 MiB  [M][K]
__device__ __half g_wh[(size_t)N_DIM * K_DIM];    // 128 MiB  [N][K]

// ---------------------------------------------------------------------------
__device__ __forceinline__ uint32_t smem_u32(const void* p) {
    uint32_t a;
    asm("{ .reg .u64 t; cvta.to.shared.u64 t, %1; cvt.u32.u64 %0, t; }" : "=r"(a) : "l"(p));
    return a;
}

__device__ __forceinline__ void cp16(uint32_t dst, const void* src) {
    asm volatile("cp.async.cg.shared.global [%0], [%1], 16;" :: "r"(dst), "l"(src));
}

#define CP_COMMIT() asm volatile("cp.async.commit_group;" ::: "memory")

__device__ __forceinline__ void ldsm4(uint32_t* r, uint32_t addr) {
    asm volatile("ldmatrix.sync.aligned.m8n8.x4.shared.b16 {%0,%1,%2,%3}, [%4];"
                 : "=r"(r[0]), "=r"(r[1]), "=r"(r[2]), "=r"(r[3]) : "r"(addr));
}

__device__ __forceinline__ void mma16816(float* d, const uint32_t* a, uint32_t b0, uint32_t b1) {
    asm volatile(
        "mma.sync.aligned.m16n8k16.row.col.f32.f16.f16.f32 "
        "{%0,%1,%2,%3}, {%4,%5,%6,%7}, {%8,%9}, {%0,%1,%2,%3};"
        : "+f"(d[0]), "+f"(d[1]), "+f"(d[2]), "+f"(d[3])
        : "r"(a[0]), "r"(a[1]), "r"(a[2]), "r"(a[3]), "r"(b0), "r"(b1));
}

__device__ __forceinline__ void stcs2(float* p, float vx, float vy) {
    asm volatile("st.global.cs.v2.f32 [%0], {%1, %2};" :: "l"(p), "f"(vx), "f"(vy) : "memory");
}

// ---------------------------------------------------------------------------
// Fused prep kernel (x convert + coalesced W transpose)
// ---------------------------------------------------------------------------
static constexpr int XB   = (M_ROWS * K_DIM / 4) / 256;   // 32768 blocks
static constexpr int WBX  = N_DIM / 32;                   // 512
static constexpr int WBY  = K_DIM / 64;                   // 64

__global__ void cvt_fused_kernel(const float4* __restrict__ x,
                                 const int* __restrict__ w,
                                 __half2* __restrict__ xh,
                                 __half* __restrict__ wh) {
    if (blockIdx.x < XB) {
        int i = blockIdx.x * 256 + threadIdx.x;
        float4 v = x[i];
        xh[2 * i]     = __floats2half2_rn(v.x, v.y);
        xh[2 * i + 1] = __floats2half2_rn(v.z, v.w);
    } else {
        __shared__ int t[64][33];
        int wb = blockIdx.x - XB;
        int n0 = (wb % WBX) * 32;
        int k0 = (wb / WBX) * 64;
        int tx = threadIdx.x & 31, ty = threadIdx.x >> 5;
        #pragma unroll
        for (int j = 0; j < 8; ++j) {
            int k = ty + 8 * j;
            t[k][tx] = w[(size_t)(k0 + k) * N_DIM + n0 + tx];
        }
        __syncthreads();
        #pragma unroll
        for (int j = 0; j < 4; ++j) {
            int i = ty + 8 * j;
            __half2 v = __halves2half2(__int2half_rn(t[2 * tx][i]),
                                       __int2half_rn(t[2 * tx + 1][i]));
            *reinterpret_cast<__half2*>(wh + (size_t)(n0 + i) * K_DIM + k0 + 2 * tx) = v;
        }
    }
}

// ---------------------------------------------------------------------------
// Main GEMM
// ---------------------------------------------------------------------------
__global__ void __launch_bounds__(128, 2) qgemm_kernel(
    const float* __restrict__ scale,
    const float* __restrict__ bias,
    float* __restrict__ out)
{
    extern __shared__ __align__(16) char smem_raw[];
    const uint32_t sb = smem_u32(smem_raw);
    const int tid = threadIdx.x;
    const int wid = tid >> 5;
    const int lid = tid & 31;

    const int bid = blockIdx.x;
    const int group  = bid >> 9;
    const int within = bid & 511;
    const int nt = (group << 3) | (within & 7);
    const int mt = within >> 3;
    const int m0 = mt * BM;
    const int n0 = nt * BN;

    // Per-thread fill addressing
    const int fa_row = tid >> 3, fa_cc = (tid & 7);
    const __half* xrow = g_xh + (size_t)(m0 + fa_row) * K_DIM + fa_cc * 8;
    const __half* wrow = g_wh + (size_t)(n0 + fa_row) * K_DIM + fa_cc * 8;
    const uint32_t a_dst0 = (uint32_t)(fa_row * A_LD + fa_cc * 8) * 2;
    const uint32_t b_dst0 = (uint32_t)(A_ST + fa_row * B_LD + fa_cc * 8) * 2;

    const int wmb = (wid & 1) * 64;
    const int wnb = (wid >> 1) * 64;

    // Prefetch scale/bias (latency hides under mainloop)
    const int ncol0 = n0 + wnb;
    float2 sc[8], bi[8];
    #pragma unroll
    for (int nf = 0; nf < 8; ++nf) {
        int c = nf * 8 + (lid & 3) * 2;
        sc[nf] = *reinterpret_cast<const float2*>(scale + ncol0 + c);
        bi[nf] = *reinterpret_cast<const float2*>(bias + ncol0 + c);
    }

    float acc[4][8][4];
    #pragma unroll
    for (int i = 0; i < 4; ++i)
        #pragma unroll
        for (int j = 0; j < 8; ++j)
            #pragma unroll
            for (int k = 0; k < 4; ++k) acc[i][j][k] = 0.0f;

    // Static stage bases (rotation handled by unrolled triple pattern)
    const uint32_t B0 = sb;
    const uint32_t B1 = sb + (uint32_t)(STG * 2);
    const uint32_t B2 = sb + (uint32_t)(2 * STG * 2);

    // Prologue: full fills of stages 0 and 1 (two commit groups each)
    #pragma unroll
    for (int s = 0; s < 2; ++s) {
        const uint32_t base = (s == 0) ? B0 : B1;
        const int k0 = s * BK;
        #pragma unroll
        for (int h = 0; h < 2; ++h) {
            #pragma unroll
            for (int p = 0; p < KSTEPS; ++p) {
                int r = (h * KSTEPS + p) * 16;
                cp16(base + a_dst0 + (uint32_t)(r * A_LD) * 2, xrow + (size_t)r * K_DIM + k0);
                cp16(base + b_dst0 + (uint32_t)(r * B_LD) * 2, wrow + (size_t)r * K_DIM + k0);
            }
            CP_COMMIT();
        }
    }

    const int a_row_lane = lid & 15;
    const int a_col_lane = (lid >> 4) * 8;
    const int b_row_lane = (lid & 7) | ((lid >> 4) << 3);
    const int b_col_lane = ((lid >> 3) & 1) * 8;

    const uint32_t a_off = (uint32_t)((wmb + a_row_lane) * A_LD + a_col_lane) * 2;
    const uint32_t b_off = (uint32_t)(A_ST + (wnb + b_row_lane) * B_LD + b_col_lane) * 2;

    int kf = 2 * BK;   // fill k-offset for stage it+2

    // Drain stage-0 groups for this thread; barrier publishes across threads.
    asm volatile("cp.async.wait_group 2;" ::: "memory");

    // One mainloop iteration with static read/write stage bases.
    auto body = [&](int it, uint32_t rd, uint32_t wr) {
        __syncthreads();
        const bool do_fill = (it + 2 < NITER);
        const __half* xp = xrow + kf;
        const __half* wp = wrow + kf;

        #pragma unroll
        for (int ks = 0; ks < KSTEPS; ++ks) {
            uint32_t a[4][4], b[4][4];
            #pragma unroll
            for (int mf = 0; mf < 4; ++mf)
                ldsm4(a[mf], rd + a_off + (uint32_t)(mf * 16 * A_LD + ks * 16) * 2);
            #pragma unroll
            for (int nf2 = 0; nf2 < 4; ++nf2)
                ldsm4(b[nf2], rd + b_off + (uint32_t)(nf2 * 16 * B_LD + ks * 16) * 2);
            if (do_fill) {
                #pragma unroll
                for (int j = 0; j < 2; ++j) {
                    int r = (ks * 2 + j) * 16;
                    cp16(wr + a_dst0 + (uint32_t)(r * A_LD) * 2, xp + (size_t)r * K_DIM);
                    cp16(wr + b_dst0 + (uint32_t)(r * B_LD) * 2, wp + (size_t)r * K_DIM);
                }
            }
            if (ks == 1 || ks == KSTEPS - 1) CP_COMMIT();
            #pragma unroll
            for (int mf = 0; mf < 4; ++mf) {
                #pragma unroll
                for (int nf2 = 0; nf2 < 4; ++nf2) {
                    mma16816(acc[mf][nf2 * 2],     a[mf], b[nf2][0], b[nf2][1]);
                    mma16816(acc[mf][nf2 * 2 + 1], a[mf], b[nf2][2], b[nf2][3]);
                }
            }
        }
        asm volatile("cp.async.wait_group 2;" ::: "memory");
        kf += BK;
    };

    // 21 triples (63 iters) + 1 tail = 64. Read stage = it%3; write = (it+2)%3.
    int it = 0;
    #pragma unroll 1
    for (int t = 0; t < NITER / 3; ++t) {
        body(it,     B0, B2);
        body(it + 1, B1, B0);
        body(it + 2, B2, B1);
        it += 3;
    }
    body(it, B0, B2);   // it = 63 (63 % 3 == 0 -> reads B0; no fill issued)

    // ---- Epilogue: fused scale/bias (prefetched), streaming stores ----
    #pragma unroll
    for (int mf = 0; mf < 4; ++mf) {
        int r0 = m0 + wmb + mf * 16 + (lid >> 2);
        float* out0 = out + (size_t)r0 * N_DIM + ncol0;
        float* out1 = out0 + (size_t)8 * N_DIM;
        #pragma unroll
        for (int nf = 0; nf < 8; ++nf) {
            int c = nf * 8 + (lid & 3) * 2;
            stcs2(out0 + c, fmaf(acc[mf][nf][0], sc[nf].x, bi[nf].x),
                            fmaf(acc[mf][nf][1], sc[nf].y, bi[nf].y));
            stcs2(out1 + c, fmaf(acc[mf][nf][2], sc[nf].x, bi[nf].x),
                            fmaf(acc[mf][nf][3], sc[nf].y, bi[nf].y));
        }
    }
}

// ---------------------------------------------------------------------------
// Host launch — inputs identified by element count.
// ---------------------------------------------------------------------------
extern "C" void kernel_launch(void* const* d_in, const int* in_sizes, int n_in,
                              void* d_out, int out_size) {
    int xi = 0, wi = 1, sm1 = -1, sm2 = -1;
    for (int i = 0; i < 4; ++i) {
        if (in_sizes[i] == M_ROWS * K_DIM)      xi = i;
        else if (in_sizes[i] == K_DIM * N_DIM)  wi = i;
        else if (sm1 < 0)                       sm1 = i;
        else                                    sm2 = i;
    }
    int si, bi2;
    if (xi < sm1) { si = sm1; bi2 = sm2; }   // dict order: x, w, scale, bias
    else          { bi2 = sm1; si = sm2; }

    const float* x     = (const float*)d_in[xi];
    const int*   w     = (const int*)d_in[wi];
    const float* scale = (const float*)d_in[si];
    const float* bias  = (const float*)d_in[bi2];
    float*       out   = (float*)d_out;

    void* xh = nullptr; cudaGetSymbolAddress(&xh, g_xh);
    void* wh = nullptr; cudaGetSymbolAddress(&wh, g_wh);

    cvt_fused_kernel<<<XB + WBX * WBY, 256>>>((const float4*)x, w,
                                              (__half2*)xh, (__half*)wh);

    cudaFuncSetAttribute(qgemm_kernel, cudaFuncAttributeMaxDynamicSharedMemorySize,
                         SMEM_BYTES);
    int grid = (M_ROWS / BM) * (N_DIM / BN);   // 8192
    qgemm_kernel<<<grid, 128, SMEM_BYTES>>>(scale, bias, out);
}

// round 16
// speedup vs baseline: 1.1343x; 1.0031x over previous
#include <cuda_runtime.h>
#include <cuda_fp16.h>
#include <cstdint>

// ---------------------------------------------------------------------------
// y[8192,16384] = x[8192,4096] @ dequant(W[4096,16384]) * scale + bias
// Weight arrives as int32 (harness dtype set is f32/i32/bf16).
// R16: GEMM byte-identical to R15 (tensor=90.6% ~= the B300 spread-floor
//      ceiling of 90.9%). Convert prologue tightened: x-convert does 8
//      floats/thread with one 16B store (2x float4 load -> uint4 store).
// ---------------------------------------------------------------------------
static constexpr int M_ROWS = 8192;
static constexpr int K_DIM  = 4096;
static constexpr int N_DIM  = 16384;

static constexpr int BM = 128;
static constexpr int BN = 128;
static constexpr int BK = 64;
static constexpr int STAGES = 3;
static constexpr int NITER  = K_DIM / BK;     // 64
static constexpr int KSTEPS = BK / 16;        // 4

static constexpr int A_LD = BK + 8;           // 72 halves = 144 B
static constexpr int B_LD = BK + 8;
static constexpr int A_ST = BM * A_LD;        // 9216 halves
static constexpr int B_ST = BN * B_LD;        // 9216 halves
static constexpr int STG  = A_ST + B_ST;      // 18432 halves = 36864 B
static constexpr int SMEM_BYTES = STAGES * STG * 2;   // 110592 B -> 2 CTAs/SM

__device__ __half g_xh[(size_t)M_ROWS * K_DIM];   //  64 MiB  [M][K]
__device__ __half g_wh[(size_t)N_DIM * K_DIM];    // 128 MiB  [N][K]

// ---------------------------------------------------------------------------
__device__ __forceinline__ uint32_t smem_u32(const void* p) {
    uint32_t a;
    asm("{ .reg .u64 t; cvta.to.shared.u64 t, %1; cvt.u32.u64 %0, t; }" : "=r"(a) : "l"(p));
    return a;
}

__device__ __forceinline__ void cp16(uint32_t dst, const void* src) {
    asm volatile("cp.async.cg.shared.global [%0], [%1], 16;" :: "r"(dst), "l"(src));
}

#define CP_COMMIT() asm volatile("cp.async.commit_group;" ::: "memory")

__device__ __forceinline__ void ldsm4(uint32_t* r, uint32_t addr) {
    asm volatile("ldmatrix.sync.aligned.m8n8.x4.shared.b16 {%0,%1,%2,%3}, [%4];"
                 : "=r"(r[0]), "=r"(r[1]), "=r"(r[2]), "=r"(r[3]) : "r"(addr));
}

__device__ __forceinline__ void mma16816(float* d, const uint32_t* a, uint32_t b0, uint32_t b1) {
    asm volatile(
        "mma.sync.aligned.m16n8k16.row.col.f32.f16.f16.f32 "
        "{%0,%1,%2,%3}, {%4,%5,%6,%7}, {%8,%9}, {%0,%1,%2,%3};"
        : "+f"(d[0]), "+f"(d[1]), "+f"(d[2]), "+f"(d[3])
        : "r"(a[0]), "r"(a[1]), "r"(a[2]), "r"(a[3]), "r"(b0), "r"(b1));
}

__device__ __forceinline__ void stcs2(float* p, float vx, float vy) {
    asm volatile("st.global.cs.v2.f32 [%0], {%1, %2};" :: "l"(p), "f"(vx), "f"(vy) : "memory");
}

// ---------------------------------------------------------------------------
// Fused prep kernel: x convert (8 floats/thread, 16B stores) + W transpose.
// ---------------------------------------------------------------------------
static constexpr int XB   = (M_ROWS * K_DIM / 8) / 256;   // 16384 blocks
static constexpr int WBX  = N_DIM / 32;                   // 512
static constexpr int WBY  = K_DIM / 64;                   // 64

__global__ void cvt_fused_kernel(const float4* __restrict__ x,
                                 const int* __restrict__ w,
                                 uint4* __restrict__ xh,
                                 __half* __restrict__ wh) {
    if (blockIdx.x < XB) {
        size_t i = (size_t)blockIdx.x * 256 + threadIdx.x;
        float4 v0 = x[2 * i];
        float4 v1 = x[2 * i + 1];
        __half2 h0 = __floats2half2_rn(v0.x, v0.y);
        __half2 h1 = __floats2half2_rn(v0.z, v0.w);
        __half2 h2 = __floats2half2_rn(v1.x, v1.y);
        __half2 h3 = __floats2half2_rn(v1.z, v1.w);
        uint4 o;
        o.x = *reinterpret_cast<uint32_t*>(&h0);
        o.y = *reinterpret_cast<uint32_t*>(&h1);
        o.z = *reinterpret_cast<uint32_t*>(&h2);
        o.w = *reinterpret_cast<uint32_t*>(&h3);
        xh[i] = o;
    } else {
        __shared__ int t[64][33];
        int wb = blockIdx.x - XB;
        int n0 = (wb % WBX) * 32;
        int k0 = (wb / WBX) * 64;
        int tx = threadIdx.x & 31, ty = threadIdx.x >> 5;
        #pragma unroll
        for (int j = 0; j < 8; ++j) {
            int k = ty + 8 * j;
            t[k][tx] = w[(size_t)(k0 + k) * N_DIM + n0 + tx];
        }
        __syncthreads();
        #pragma unroll
        for (int j = 0; j < 4; ++j) {
            int i = ty + 8 * j;
            __half2 v = __halves2half2(__int2half_rn(t[2 * tx][i]),
                                       __int2half_rn(t[2 * tx + 1][i]));
            *reinterpret_cast<__half2*>(wh + (size_t)(n0 + i) * K_DIM + k0 + 2 * tx) = v;
        }
    }
}

// ---------------------------------------------------------------------------
// Main GEMM — byte-identical to R15 (at the spread-floor ceiling).
// ---------------------------------------------------------------------------
__global__ void __launch_bounds__(128, 2) qgemm_kernel(
    const float* __restrict__ scale,
    const float* __restrict__ bias,
    float* __restrict__ out)
{
    extern __shared__ __align__(16) char smem_raw[];
    const uint32_t sb = smem_u32(smem_raw);
    const int tid = threadIdx.x;
    const int wid = tid >> 5;
    const int lid = tid & 31;

    const int bid = blockIdx.x;
    const int group  = bid >> 9;
    const int within = bid & 511;
    const int nt = (group << 3) | (within & 7);
    const int mt = within >> 3;
    const int m0 = mt * BM;
    const int n0 = nt * BN;

    // Per-thread fill addressing
    const int fa_row = tid >> 3, fa_cc = (tid & 7);
    const __half* xrow = g_xh + (size_t)(m0 + fa_row) * K_DIM + fa_cc * 8;
    const __half* wrow = g_wh + (size_t)(n0 + fa_row) * K_DIM + fa_cc * 8;
    const uint32_t a_dst0 = (uint32_t)(fa_row * A_LD + fa_cc * 8) * 2;
    const uint32_t b_dst0 = (uint32_t)(A_ST + fa_row * B_LD + fa_cc * 8) * 2;

    const int wmb = (wid & 1) * 64;
    const int wnb = (wid >> 1) * 64;

    // Prefetch scale/bias (latency hides under mainloop)
    const int ncol0 = n0 + wnb;
    float2 sc[8], bi[8];
    #pragma unroll
    for (int nf = 0; nf < 8; ++nf) {
        int c = nf * 8 + (lid & 3) * 2;
        sc[nf] = *reinterpret_cast<const float2*>(scale + ncol0 + c);
        bi[nf] = *reinterpret_cast<const float2*>(bias + ncol0 + c);
    }

    float acc[4][8][4];
    #pragma unroll
    for (int i = 0; i < 4; ++i)
        #pragma unroll
        for (int j = 0; j < 8; ++j)
            #pragma unroll
            for (int k = 0; k < 4; ++k) acc[i][j][k] = 0.0f;

    // Static stage bases (rotation handled by unrolled triple pattern)
    const uint32_t B0 = sb;
    const uint32_t B1 = sb + (uint32_t)(STG * 2);
    const uint32_t B2 = sb + (uint32_t)(2 * STG * 2);

    // Prologue: full fills of stages 0 and 1 (two commit groups each)
    #pragma unroll
    for (int s = 0; s < 2; ++s) {
        const uint32_t base = (s == 0) ? B0 : B1;
        const int k0 = s * BK;
        #pragma unroll
        for (int h = 0; h < 2; ++h) {
            #pragma unroll
            for (int p = 0; p < KSTEPS; ++p) {
                int r = (h * KSTEPS + p) * 16;
                cp16(base + a_dst0 + (uint32_t)(r * A_LD) * 2, xrow + (size_t)r * K_DIM + k0);
                cp16(base + b_dst0 + (uint32_t)(r * B_LD) * 2, wrow + (size_t)r * K_DIM + k0);
            }
            CP_COMMIT();
        }
    }

    const int a_row_lane = lid & 15;
    const int a_col_lane = (lid >> 4) * 8;
    const int b_row_lane = (lid & 7) | ((lid >> 4) << 3);
    const int b_col_lane = ((lid >> 3) & 1) * 8;

    const uint32_t a_off = (uint32_t)((wmb + a_row_lane) * A_LD + a_col_lane) * 2;
    const uint32_t b_off = (uint32_t)(A_ST + (wnb + b_row_lane) * B_LD + b_col_lane) * 2;

    int kf = 2 * BK;   // fill k-offset for stage it+2

    asm volatile("cp.async.wait_group 2;" ::: "memory");

    auto body = [&](int it, uint32_t rd, uint32_t wr) {
        __syncthreads();
        const bool do_fill = (it + 2 < NITER);
        const __half* xp = xrow + kf;
        const __half* wp = wrow + kf;

        #pragma unroll
        for (int ks = 0; ks < KSTEPS; ++ks) {
            uint32_t a[4][4], b[4][4];
            #pragma unroll
            for (int mf = 0; mf < 4; ++mf)
                ldsm4(a[mf], rd + a_off + (uint32_t)(mf * 16 * A_LD + ks * 16) * 2);
            #pragma unroll
            for (int nf2 = 0; nf2 < 4; ++nf2)
                ldsm4(b[nf2], rd + b_off + (uint32_t)(nf2 * 16 * B_LD + ks * 16) * 2);
            if (do_fill) {
                #pragma unroll
                for (int j = 0; j < 2; ++j) {
                    int r = (ks * 2 + j) * 16;
                    cp16(wr + a_dst0 + (uint32_t)(r * A_LD) * 2, xp + (size_t)r * K_DIM);
                    cp16(wr + b_dst0 + (uint32_t)(r * B_LD) * 2, wp + (size_t)r * K_DIM);
                }
            }
            if (ks == 1 || ks == KSTEPS - 1) CP_COMMIT();
            #pragma unroll
            for (int mf = 0; mf < 4; ++mf) {
                #pragma unroll
                for (int nf2 = 0; nf2 < 4; ++nf2) {
                    mma16816(acc[mf][nf2 * 2],     a[mf], b[nf2][0], b[nf2][1]);
                    mma16816(acc[mf][nf2 * 2 + 1], a[mf], b[nf2][2], b[nf2][3]);
                }
            }
        }
        asm volatile("cp.async.wait_group 2;" ::: "memory");
        kf += BK;
    };

    // 21 triples (63 iters) + 1 tail = 64. Read stage = it%3; write = (it+2)%3.
    int it = 0;
    #pragma unroll 1
    for (int t = 0; t < NITER / 3; ++t) {
        body(it,     B0, B2);
        body(it + 1, B1, B0);
        body(it + 2, B2, B1);
        it += 3;
    }
    body(it, B0, B2);   // it = 63 reads B0; no fill issued

    // ---- Epilogue: fused scale/bias (prefetched), streaming stores ----
    #pragma unroll
    for (int mf = 0; mf < 4; ++mf) {
        int r0 = m0 + wmb + mf * 16 + (lid >> 2);
        float* out0 = out + (size_t)r0 * N_DIM + ncol0;
        float* out1 = out0 + (size_t)8 * N_DIM;
        #pragma unroll
        for (int nf = 0; nf < 8; ++nf) {
            int c = nf * 8 + (lid & 3) * 2;
            stcs2(out0 + c, fmaf(acc[mf][nf][0], sc[nf].x, bi[nf].x),
                            fmaf(acc[mf][nf][1], sc[nf].y, bi[nf].y));
            stcs2(out1 + c, fmaf(acc[mf][nf][2], sc[nf].x, bi[nf].x),
                            fmaf(acc[mf][nf][3], sc[nf].y, bi[nf].y));
        }
    }
}

// ---------------------------------------------------------------------------
// Host launch — inputs identified by element count.
// ---------------------------------------------------------------------------
extern "C" void kernel_launch(void* const* d_in, const int* in_sizes, int n_in,
                              void* d_out, int out_size) {
    int xi = 0, wi = 1, sm1 = -1, sm2 = -1;
    for (int i = 0; i < 4; ++i) {
        if (in_sizes[i] == M_ROWS * K_DIM)      xi = i;
        else if (in_sizes[i] == K_DIM * N_DIM)  wi = i;
        else if (sm1 < 0)                       sm1 = i;
        else                                    sm2 = i;
    }
    int si, bi2;
    if (xi < sm1) { si = sm1; bi2 = sm2; }   // dict order: x, w, scale, bias
    else          { bi2 = sm1; si = sm2; }

    const float* x     = (const float*)d_in[xi];
    const int*   w     = (const int*)d_in[wi];
    const float* scale = (const float*)d_in[si];
    const float* bias  = (const float*)d_in[bi2];
    float*       out   = (float*)d_out;

    void* xh = nullptr; cudaGetSymbolAddress(&xh, g_xh);
    void* wh = nullptr; cudaGetSymbolAddress(&wh, g_wh);

    cvt_fused_kernel<<<XB + WBX * WBY, 256>>>((const float4*)x, w,
                                              (uint4*)xh, (__half*)wh);

    cudaFuncSetAttribute(qgemm_kernel, cudaFuncAttributeMaxDynamicSharedMemorySize,
                         SMEM_BYTES);
    int grid = (M_ROWS / BM) * (N_DIM / BN);   // 8192
    qgemm_kernel<<<grid, 128, SMEM_BYTES>>>(scale, bias, out);
}